// round 12
// baseline (speedup 1.0000x reference)
#include <cuda_runtime.h>
#include <cuda_bf16.h>

#define N_NODES 100000
#define N_EDGES 3200000
#define D_FEAT  512
#define HIDDEN  16
#define N_CLS   40
#define SCAN_BLK 1024
#define N_SCAN_BLKS ((N_NODES + SCAN_BLK - 1) / SCAN_BLK)   // 98
#define KTILE 8
#define XSTRIDE 257

// ---------------- scratch (static device globals; no allocation) -------------
__device__ int    d_is64;
__device__ int    d_src [N_EDGES];
__device__ int    d_dst [N_EDGES];
__device__ int    d_csr_src[N_EDGES];          // src ids grouped by dst
__device__ int    d_deg [N_NODES];             // incoming edge count (no self)
__device__ int    d_ptr [N_NODES];             // exclusive prefix of deg
__device__ int    d_fill[N_NODES];
__device__ int    d_bsum[N_SCAN_BLKS];
__device__ float  d_dinv[N_NODES];
__device__ float4 d_g1  [N_NODES * 4];         // dinv[v] * (x[v] @ W1)
__device__ float4 d_g2  [N_NODES * 4];         // dinv[v] * relu(...)

__device__ __forceinline__ float4 f4fma(float a, float4 b, float4 c) {
    c.x = fmaf(a, b.x, c.x); c.y = fmaf(a, b.y, c.y);
    c.z = fmaf(a, b.z, c.z); c.w = fmaf(a, b.w, c.w);
    return c;
}
__device__ __forceinline__ float4 f4scale(float a, float4 b) {
    return make_float4(a * b.x, a * b.y, a * b.z, a * b.w);
}
__device__ __forceinline__ float4 f4add(float4 a, float4 b) {
    return make_float4(a.x + b.x, a.y + b.y, a.z + b.z, a.w + b.w);
}

// ---------------- 0) edge dtype detect (parallel) -----------------------------
__global__ void k_detect(const void* __restrict__ ei) {
    const unsigned long long* p = (const unsigned long long*)ei;
    int t = threadIdx.x;                       // 32 threads
    unsigned long long a = p[t];
    unsigned long long b = p[t + 32];
    int ok = (a < (unsigned long long)N_NODES) && (b < (unsigned long long)N_NODES);
    unsigned m = __ballot_sync(0xffffffff, ok);
    if (t == 0) d_is64 = (m == 0xffffffffu) ? 1 : 0;
}

// ---------------- 1a) zero counters ------------------------------------------
__global__ void k_init() {
    int i = blockIdx.x * blockDim.x + threadIdx.x;
    if (i < N_NODES) { d_deg[i] = 0; d_fill[i] = 0; }
}

// ---------------- 1b) decode edges + count degrees ---------------------------
__global__ void __launch_bounds__(256) k_decode(const void* __restrict__ ei) {
    int i = blockIdx.x * blockDim.x + threadIdx.x;
    if (i >= N_EDGES) return;
    int s, d;
    if (d_is64) {
        const long long* p = (const long long*)ei;
        s = (int)p[i];
        d = (int)p[i + N_EDGES];
    } else {
        const int* p = (const int*)ei;
        s = p[i];
        d = p[i + N_EDGES];
    }
    d_src[i] = s;
    d_dst[i] = d;
    if ((unsigned)d < N_NODES) atomicAdd(&d_deg[d], 1);
}

// ---------------- 2) prefix scan of deg -> ptr  (+ dinv fused) ----------------
__global__ void __launch_bounds__(SCAN_BLK) k_scan1() {
    __shared__ int sm[SCAN_BLK];
    int t = threadIdx.x;
    int i = blockIdx.x * SCAN_BLK + t;
    int val = (i < N_NODES) ? d_deg[i] : 0;
    if (i < N_NODES) d_dinv[i] = rsqrtf((float)(val + 1));
    sm[t] = val;
    __syncthreads();
#pragma unroll
    for (int off = 1; off < SCAN_BLK; off <<= 1) {
        int x = (t >= off) ? sm[t - off] : 0;
        __syncthreads();
        sm[t] += x;
        __syncthreads();
    }
    if (i < N_NODES) d_ptr[i] = sm[t] - val;        // exclusive, pre-offset
    if (t == SCAN_BLK - 1) d_bsum[blockIdx.x] = sm[t];
}
__global__ void __launch_bounds__(128) k_scan2() {
    __shared__ int sm[128];
    int t = threadIdx.x;
    int v = (t < N_SCAN_BLKS) ? d_bsum[t] : 0;
    sm[t] = v;
    __syncthreads();
#pragma unroll
    for (int off = 1; off < 128; off <<= 1) {
        int x = (t >= off) ? sm[t - off] : 0;
        __syncthreads();
        sm[t] += x;
        __syncthreads();
    }
    if (t < N_SCAN_BLKS) d_bsum[t] = sm[t] - v;     // exclusive block offsets
}
__global__ void k_scan3() {
    int i = blockIdx.x * blockDim.x + threadIdx.x;
    if (i < N_NODES) d_ptr[i] += d_bsum[i / SCAN_BLK];
}

// ---------------- 3) bucket fill: csr_src grouped by dst ----------------------
__global__ void __launch_bounds__(256) k_fill() {
    int i = blockIdx.x * blockDim.x + threadIdx.x;
    if (i >= N_EDGES) return;
    unsigned s = (unsigned)d_src[i];
    unsigned d = (unsigned)d_dst[i];
    if (s >= N_NODES || d >= N_NODES) return;
    int pos = d_ptr[d] + atomicAdd(&d_fill[d], 1);
    d_csr_src[pos] = (int)s;
}

// ---------------- 4) GEMM1: g1 = dinv * (x @ W1) ------------------------------
// Coalesced smem-staged transpose (padded, conflict-free reads), plain FFMA,
// thread-per-row. 41 KB smem -> 5 blocks/SM. Computes own dinv (slot-3 profiling).
__global__ void __launch_bounds__(256) k_gemm1(const float* __restrict__ x,
                                               const float* __restrict__ W1) {
    __shared__ float4 Ws[D_FEAT * 4];            // 32 KB : Ws[k*4 + c4]
    __shared__ float  xs[KTILE * XSTRIDE];       // 8.2 KB: xs[k][row], padded
    int t = threadIdx.x;

    for (int i = t; i < D_FEAT * 4; i += 256) Ws[i] = ((const float4*)W1)[i];

    int row0 = blockIdx.x * 256;
    int row  = row0 + t;
    bool valid = row < N_NODES;
    int kq   = t & 1;                  // float4 slot within 8-k tile
    int rsub = t >> 1;                 // 0..127 : row within staging wave

    float4 a0 = make_float4(0.f, 0.f, 0.f, 0.f);
    float4 a1 = a0, a2 = a0, a3 = a0;

#pragma unroll 1
    for (int kt = 0; kt < D_FEAT / KTILE; kt++) {
        int k0 = kt * KTILE;
        __syncthreads();               // protect prior tile reads (and Ws, 1st iter)
#pragma unroll
        for (int i = 0; i < 2; i++) {
            int rl = i * 128 + rsub;
            int gr = row0 + rl;
            float4 v = make_float4(0.f, 0.f, 0.f, 0.f);
            if (gr < N_NODES)
                v = *(const float4*)(x + (size_t)gr * D_FEAT + k0 + kq * 4);
            xs[(kq * 4 + 0) * XSTRIDE + rl] = v.x;
            xs[(kq * 4 + 1) * XSTRIDE + rl] = v.y;
            xs[(kq * 4 + 2) * XSTRIDE + rl] = v.z;
            xs[(kq * 4 + 3) * XSTRIDE + rl] = v.w;
        }
        __syncthreads();

#pragma unroll
        for (int kk = 0; kk < KTILE; kk++) {
            float xk = xs[kk * XSTRIDE + t];
            const float4* w = &Ws[(k0 + kk) * 4];
            a0 = f4fma(xk, w[0], a0);
            a1 = f4fma(xk, w[1], a1);
            a2 = f4fma(xk, w[2], a2);
            a3 = f4fma(xk, w[3], a3);
        }
    }

    if (!valid) return;
    float dv = rsqrtf((float)(d_deg[row] + 1));     // dinv computed locally
    d_g1[(size_t)row * 4 + 0] = f4scale(dv, a0);
    d_g1[(size_t)row * 4 + 1] = f4scale(dv, a1);
    d_g1[(size_t)row * 4 + 2] = f4scale(dv, a2);
    d_g1[(size_t)row * 4 + 3] = f4scale(dv, a3);
}

// ---------------- warp-gather reduction helper --------------------------------
__device__ __forceinline__ float4 warp_aggregate(int v, int lane,
                                                 const float4* __restrict__ g) {
    int q   = lane & 3;
    int sub = lane >> 2;
    int beg = d_ptr[v];
    int end = beg + d_deg[v];
    float4 acc = make_float4(0.f, 0.f, 0.f, 0.f);
    for (int e = beg + sub; e < end; e += 8) {
        int s = d_csr_src[e];
        acc = f4add(acc, __ldg(&g[(size_t)s * 4 + q]));
    }
#pragma unroll
    for (int off = 16; off >= 4; off >>= 1) {
        acc.x += __shfl_xor_sync(0xffffffff, acc.x, off);
        acc.y += __shfl_xor_sync(0xffffffff, acc.y, off);
        acc.z += __shfl_xor_sync(0xffffffff, acc.z, off);
        acc.w += __shfl_xor_sync(0xffffffff, acc.w, off);
    }
    return acc;
}

// ---------------- 5) aggr1 + mid: g2 = dinv * relu(dinv*(sum+self) + b1) ------
__global__ void __launch_bounds__(256) k_aggr1(const float* __restrict__ b1) {
    int v = blockIdx.x * 8 + (threadIdx.x >> 5);
    if (v >= N_NODES) return;
    int lane = threadIdx.x & 31;
    int q = lane & 3;

    float4 acc = warp_aggregate(v, lane, d_g1);
    if ((lane >> 2) == 0) {
        float dv = d_dinv[v];
        float4 a = f4add(acc, d_g1[(size_t)v * 4 + q]);   // + self loop
        float4 b = __ldg(&((const float4*)b1)[q]);
        float4 h;
        h.x = fmaxf(fmaf(dv, a.x, b.x), 0.f);
        h.y = fmaxf(fmaf(dv, a.y, b.y), 0.f);
        h.z = fmaxf(fmaf(dv, a.z, b.z), 0.f);
        h.w = fmaxf(fmaf(dv, a.w, b.w), 0.f);
        d_g2[(size_t)v * 4 + q] = f4scale(dv, h);
    }
}

// ---------------- 6) aggr2 + final: out = (dinv*(sum+self)) @ W2 + b2 ---------
__global__ void __launch_bounds__(256) k_aggr2(const float* __restrict__ W2,
                                               const float* __restrict__ b2,
                                               float* __restrict__ out) {
    __shared__ float W2s[HIDDEN * N_CLS];
    __shared__ float b2s[N_CLS];
    for (int i = threadIdx.x; i < HIDDEN * N_CLS; i += 256) W2s[i] = W2[i];
    if (threadIdx.x < N_CLS) b2s[threadIdx.x] = b2[threadIdx.x];
    __syncthreads();

    int v = blockIdx.x * 8 + (threadIdx.x >> 5);
    if (v >= N_NODES) return;
    int lane = threadIdx.x & 31;
    int q = lane & 3;

    float4 acc = warp_aggregate(v, lane, d_g2);
    float dv = d_dinv[v];
    float4 a4 = f4scale(dv, f4add(acc, d_g2[(size_t)v * 4 + q]));
    float comp[4] = {a4.x, a4.y, a4.z, a4.w};

    int c1 = 32 + (lane & 7);
    float o0 = b2s[lane];
    float o1 = b2s[c1];
#pragma unroll
    for (int k = 0; k < HIDDEN; k++) {
        float ak = __shfl_sync(0xffffffff, comp[k & 3], k >> 2);
        o0 = fmaf(ak, W2s[k * N_CLS + lane], o0);
        o1 = fmaf(ak, W2s[k * N_CLS + c1], o1);
    }
    out[(size_t)v * N_CLS + lane] = o0;
    if (lane < 8) out[(size_t)v * N_CLS + c1] = o1;
}

// ---------------- launch ------------------------------------------------------
extern "C" void kernel_launch(void* const* d_in, const int* in_sizes, int n_in,
                              void* d_out, int out_size) {
    const float* x  = nullptr;  const void* ei = nullptr;
    const float* W1 = nullptr;  const float* b1 = nullptr;
    const float* W2 = nullptr;  const float* b2 = nullptr;
    for (int i = 0; i < n_in; i++) {
        long long sz = in_sizes[i];
        if      (sz == (long long)N_NODES * D_FEAT) x  = (const float*)d_in[i];
        else if (sz == 2LL * N_EDGES)               ei = d_in[i];
        else if (sz == (long long)D_FEAT * HIDDEN)  W1 = (const float*)d_in[i];
        else if (sz == HIDDEN)                      b1 = (const float*)d_in[i];
        else if (sz == (long long)HIDDEN * N_CLS)   W2 = (const float*)d_in[i];
        else if (sz == N_CLS)                       b2 = (const float*)d_in[i];
    }
    float* out = (float*)d_out;

    const int TB = 256;
    int nb_n = (N_NODES + TB - 1) / TB;
    int nb_e = (N_EDGES + TB - 1) / TB;
    int nb_w = (N_NODES + 7) / 8;          // warp-per-node kernels

    k_detect<<<1, 32>>>(ei);               // launch 0
    k_init<<<nb_n, TB>>>();                // launch 1
    k_decode<<<nb_e, TB>>>(ei);            // launch 2
    k_gemm1<<<nb_n, TB>>>(x, W1);          // launch 3  <-- ncu profiling slot
    k_scan1<<<N_SCAN_BLKS, SCAN_BLK>>>();  // launch 4
    k_scan2<<<1, 128>>>();
    k_scan3<<<nb_n, TB>>>();
    k_fill<<<nb_e, TB>>>();
    k_aggr1<<<nb_w, TB>>>(b1);
    k_aggr2<<<nb_w, TB>>>(W2, b2, out);
}

// round 14
// speedup vs baseline: 1.0858x; 1.0858x over previous
#include <cuda_runtime.h>
#include <cuda_bf16.h>

#define N_NODES 100000
#define N_EDGES 3200000
#define D_FEAT  512
#define HIDDEN  16
#define N_CLS   40
#define SCAN_BLK 1024
#define N_SCAN_BLKS ((N_NODES + SCAN_BLK - 1) / SCAN_BLK)   // 98
#define KTILE 16

// ---------------- scratch (static device globals; no allocation) -------------
__device__ int    d_is64;
__device__ int    d_src [N_EDGES];
__device__ int    d_dst [N_EDGES];
__device__ int    d_csr_src[N_EDGES];          // src ids grouped by dst
__device__ int    d_deg [N_NODES];             // incoming edge count (no self)
__device__ int    d_ptr [N_NODES];             // exclusive prefix of deg
__device__ int    d_fill[N_NODES];
__device__ int    d_bsum[N_SCAN_BLKS];
__device__ float  d_dinv[N_NODES];
__device__ float4 d_g1  [N_NODES * 4];         // dinv[v] * (x[v] @ W1)
__device__ float4 d_g2  [N_NODES * 4];         // dinv[v] * relu(...)

__device__ __forceinline__ float4 f4scale(float a, float4 b) {
    return make_float4(a * b.x, a * b.y, a * b.z, a * b.w);
}
__device__ __forceinline__ float4 f4add(float4 a, float4 b) {
    return make_float4(a.x + b.x, a.y + b.y, a.z + b.z, a.w + b.w);
}

// ---------------- 0) edge dtype detect (parallel) -----------------------------
__global__ void k_detect(const void* __restrict__ ei) {
    const unsigned long long* p = (const unsigned long long*)ei;
    int t = threadIdx.x;                       // 32 threads
    unsigned long long a = p[t];
    unsigned long long b = p[t + 32];
    int ok = (a < (unsigned long long)N_NODES) && (b < (unsigned long long)N_NODES);
    unsigned m = __ballot_sync(0xffffffff, ok);
    if (t == 0) d_is64 = (m == 0xffffffffu) ? 1 : 0;
}

// ---------------- 1a) zero counters ------------------------------------------
__global__ void k_init() {
    int i = blockIdx.x * blockDim.x + threadIdx.x;
    if (i < N_NODES) { d_deg[i] = 0; d_fill[i] = 0; }
}

// ---------------- 1b) decode edges + count degrees ---------------------------
__global__ void __launch_bounds__(256) k_decode(const void* __restrict__ ei) {
    int i = blockIdx.x * blockDim.x + threadIdx.x;
    if (i >= N_EDGES) return;
    int s, d;
    if (d_is64) {
        const long long* p = (const long long*)ei;
        s = (int)p[i];
        d = (int)p[i + N_EDGES];
    } else {
        const int* p = (const int*)ei;
        s = p[i];
        d = p[i + N_EDGES];
    }
    d_src[i] = s;
    d_dst[i] = d;
    if ((unsigned)d < N_NODES) atomicAdd(&d_deg[d], 1);
}

// ---------------- 2) prefix scan of deg -> ptr  (+ dinv fused) ----------------
__global__ void __launch_bounds__(SCAN_BLK) k_scan1() {
    __shared__ int sm[SCAN_BLK];
    int t = threadIdx.x;
    int i = blockIdx.x * SCAN_BLK + t;
    int val = (i < N_NODES) ? d_deg[i] : 0;
    if (i < N_NODES) d_dinv[i] = rsqrtf((float)(val + 1));
    sm[t] = val;
    __syncthreads();
#pragma unroll
    for (int off = 1; off < SCAN_BLK; off <<= 1) {
        int x = (t >= off) ? sm[t - off] : 0;
        __syncthreads();
        sm[t] += x;
        __syncthreads();
    }
    if (i < N_NODES) d_ptr[i] = sm[t] - val;        // exclusive, pre-offset
    if (t == SCAN_BLK - 1) d_bsum[blockIdx.x] = sm[t];
}
__global__ void __launch_bounds__(128) k_scan2() {
    __shared__ int sm[128];
    int t = threadIdx.x;
    int v = (t < N_SCAN_BLKS) ? d_bsum[t] : 0;
    sm[t] = v;
    __syncthreads();
#pragma unroll
    for (int off = 1; off < 128; off <<= 1) {
        int x = (t >= off) ? sm[t - off] : 0;
        __syncthreads();
        sm[t] += x;
        __syncthreads();
    }
    if (t < N_SCAN_BLKS) d_bsum[t] = sm[t] - v;     // exclusive block offsets
}
__global__ void k_scan3() {
    int i = blockIdx.x * blockDim.x + threadIdx.x;
    if (i < N_NODES) d_ptr[i] += d_bsum[i / SCAN_BLK];
}

// ---------------- 3) bucket fill: csr_src grouped by dst ----------------------
__global__ void __launch_bounds__(256) k_fill() {
    int i = blockIdx.x * blockDim.x + threadIdx.x;
    if (i >= N_EDGES) return;
    unsigned s = (unsigned)d_src[i];
    unsigned d = (unsigned)d_dst[i];
    if (s >= N_NODES || d >= N_NODES) return;
    int pos = d_ptr[d] + atomicAdd(&d_fill[d], 1);
    d_csr_src[pos] = (int)s;
}

// ---------------- 4) GEMM1: g1 = dinv * (x @ W1) ------------------------------
// thread = (col-quarter q, row-slot rr); computes 4 rows x 4 cols.
// Per k: one 16-byte W read (4 cols), 4 broadcast xk reads, 8 FFMA2.
// All smem loads are plain C++ (ordered by __syncthreads; no CSE hazard).
__global__ void __launch_bounds__(256) k_gemm1(const float* __restrict__ x,
                                               const float* __restrict__ W1) {
    __shared__ unsigned long long Wp[D_FEAT * 8];   // 32 KB : col-pairs per k
    __shared__ float xs[KTILE * 256];               // 16 KB : xs[k][row]
    int t = threadIdx.x;

    for (int i = t; i < D_FEAT * 8; i += 256) {
        float2 p = ((const float2*)W1)[i];
        unsigned long long u;
        asm("mov.b64 %0, {%1,%2};" : "=l"(u)
            : "r"(__float_as_uint(p.x)), "r"(__float_as_uint(p.y)));
        Wp[i] = u;
    }

    int row0 = blockIdx.x * 256;
    int q  = t & 3;                    // col-quarter (cols 4q..4q+3)
    int rr = t >> 2;                   // row-slot 0..63

    // acc[i][j]: row (row0 + i*64 + rr), col-pair j of this quarter
    unsigned long long acc[4][2] = {{0,0},{0,0},{0,0},{0,0}};

#pragma unroll 1
    for (int kt = 0; kt < D_FEAT / KTILE; kt++) {
        int k0 = kt * KTILE;
        __syncthreads();
        // stage 256 rows x 16 k, transposed (4 waves of 64 rows)
#pragma unroll
        for (int i = 0; i < 4; i++) {
            int rl = i * 64 + rr;
            int gr = row0 + rl;
            float4 v = make_float4(0.f, 0.f, 0.f, 0.f);
            if (gr < N_NODES)
                v = *(const float4*)(x + (size_t)gr * D_FEAT + k0 + q * 4);
            xs[(q * 4 + 0) * 256 + rl] = v.x;
            xs[(q * 4 + 1) * 256 + rl] = v.y;
            xs[(q * 4 + 2) * 256 + rl] = v.z;
            xs[(q * 4 + 3) * 256 + rl] = v.w;
        }
        __syncthreads();

#pragma unroll
        for (int kk = 0; kk < KTILE; kk++) {
            unsigned long long w0 = Wp[(k0 + kk) * 8 + q * 2];
            unsigned long long w1 = Wp[(k0 + kk) * 8 + q * 2 + 1];
#pragma unroll
            for (int i = 0; i < 4; i++) {
                float xk = xs[kk * 256 + i * 64 + rr];
                unsigned long long bx;
                asm("mov.b64 %0, {%1, %1};" : "=l"(bx) : "r"(__float_as_uint(xk)));
                asm("fma.rn.f32x2 %0, %1, %2, %0;" : "+l"(acc[i][0]) : "l"(w0), "l"(bx));
                asm("fma.rn.f32x2 %0, %1, %2, %0;" : "+l"(acc[i][1]) : "l"(w1), "l"(bx));
            }
        }
    }

#pragma unroll
    for (int i = 0; i < 4; i++) {
        int row = row0 + i * 64 + rr;
        if (row >= N_NODES) continue;
        unsigned f0, f1, f2, f3;
        asm("mov.b64 {%0,%1}, %2;" : "=r"(f0), "=r"(f1) : "l"(acc[i][0]));
        asm("mov.b64 {%0,%1}, %2;" : "=r"(f2), "=r"(f3) : "l"(acc[i][1]));
        float dv = rsqrtf((float)(d_deg[row] + 1));
        d_g1[(size_t)row * 4 + q] =
            make_float4(dv * __uint_as_float(f0), dv * __uint_as_float(f1),
                        dv * __uint_as_float(f2), dv * __uint_as_float(f3));
    }
}

// ---------------- warp-gather reduction helper --------------------------------
__device__ __forceinline__ float4 warp_aggregate(int v, int lane,
                                                 const float4* __restrict__ g) {
    int q   = lane & 3;
    int sub = lane >> 2;
    int beg = d_ptr[v];
    int end = beg + d_deg[v];
    float4 acc = make_float4(0.f, 0.f, 0.f, 0.f);
    for (int e = beg + sub; e < end; e += 8) {
        int s = d_csr_src[e];
        acc = f4add(acc, __ldg(&g[(size_t)s * 4 + q]));
    }
#pragma unroll
    for (int off = 16; off >= 4; off >>= 1) {
        acc.x += __shfl_xor_sync(0xffffffff, acc.x, off);
        acc.y += __shfl_xor_sync(0xffffffff, acc.y, off);
        acc.z += __shfl_xor_sync(0xffffffff, acc.z, off);
        acc.w += __shfl_xor_sync(0xffffffff, acc.w, off);
    }
    return acc;
}

// ---------------- 5) aggr1 + mid: g2 = dinv * relu(dinv*(sum+self) + b1) ------
__global__ void __launch_bounds__(256) k_aggr1(const float* __restrict__ b1) {
    int v = blockIdx.x * 8 + (threadIdx.x >> 5);
    if (v >= N_NODES) return;
    int lane = threadIdx.x & 31;
    int q = lane & 3;

    float4 acc = warp_aggregate(v, lane, d_g1);
    if ((lane >> 2) == 0) {
        float dv = d_dinv[v];
        float4 a = f4add(acc, d_g1[(size_t)v * 4 + q]);   // + self loop
        float4 b = __ldg(&((const float4*)b1)[q]);
        float4 h;
        h.x = fmaxf(fmaf(dv, a.x, b.x), 0.f);
        h.y = fmaxf(fmaf(dv, a.y, b.y), 0.f);
        h.z = fmaxf(fmaf(dv, a.z, b.z), 0.f);
        h.w = fmaxf(fmaf(dv, a.w, b.w), 0.f);
        d_g2[(size_t)v * 4 + q] = f4scale(dv, h);
    }
}

// ---------------- 6) aggr2 + final: out = (dinv*(sum+self)) @ W2 + b2 ---------
__global__ void __launch_bounds__(256) k_aggr2(const float* __restrict__ W2,
                                               const float* __restrict__ b2,
                                               float* __restrict__ out) {
    __shared__ float W2s[HIDDEN * N_CLS];
    __shared__ float b2s[N_CLS];
    for (int i = threadIdx.x; i < HIDDEN * N_CLS; i += 256) W2s[i] = W2[i];
    if (threadIdx.x < N_CLS) b2s[threadIdx.x] = b2[threadIdx.x];
    __syncthreads();

    int v = blockIdx.x * 8 + (threadIdx.x >> 5);
    if (v >= N_NODES) return;
    int lane = threadIdx.x & 31;
    int q = lane & 3;

    float4 acc = warp_aggregate(v, lane, d_g2);
    float dv = d_dinv[v];
    float4 a4 = f4scale(dv, f4add(acc, d_g2[(size_t)v * 4 + q]));
    float comp[4] = {a4.x, a4.y, a4.z, a4.w};

    int c1 = 32 + (lane & 7);
    float o0 = b2s[lane];
    float o1 = b2s[c1];
#pragma unroll
    for (int k = 0; k < HIDDEN; k++) {
        float ak = __shfl_sync(0xffffffff, comp[k & 3], k >> 2);
        o0 = fmaf(ak, W2s[k * N_CLS + lane], o0);
        o1 = fmaf(ak, W2s[k * N_CLS + c1], o1);
    }
    out[(size_t)v * N_CLS + lane] = o0;
    if (lane < 8) out[(size_t)v * N_CLS + c1] = o1;
}

// ---------------- launch ------------------------------------------------------
extern "C" void kernel_launch(void* const* d_in, const int* in_sizes, int n_in,
                              void* d_out, int out_size) {
    const float* x  = nullptr;  const void* ei = nullptr;
    const float* W1 = nullptr;  const float* b1 = nullptr;
    const float* W2 = nullptr;  const float* b2 = nullptr;
    for (int i = 0; i < n_in; i++) {
        long long sz = in_sizes[i];
        if      (sz == (long long)N_NODES * D_FEAT) x  = (const float*)d_in[i];
        else if (sz == 2LL * N_EDGES)               ei = d_in[i];
        else if (sz == (long long)D_FEAT * HIDDEN)  W1 = (const float*)d_in[i];
        else if (sz == HIDDEN)                      b1 = (const float*)d_in[i];
        else if (sz == (long long)HIDDEN * N_CLS)   W2 = (const float*)d_in[i];
        else if (sz == N_CLS)                       b2 = (const float*)d_in[i];
    }
    float* out = (float*)d_out;

    const int TB = 256;
    int nb_n = (N_NODES + TB - 1) / TB;
    int nb_e = (N_EDGES + TB - 1) / TB;
    int nb_w = (N_NODES + 7) / 8;          // warp-per-node kernels

    k_detect<<<1, 32>>>(ei);               // launch 0
    k_init<<<nb_n, TB>>>();                // launch 1
    k_decode<<<nb_e, TB>>>(ei);            // launch 2
    k_gemm1<<<nb_n, TB>>>(x, W1);          // launch 3  <-- ncu profiling slot
    k_scan1<<<N_SCAN_BLKS, SCAN_BLK>>>();  // launch 4
    k_scan2<<<1, 128>>>();
    k_scan3<<<nb_n, TB>>>();
    k_fill<<<nb_e, TB>>>();
    k_aggr1<<<nb_w, TB>>>(b1);
    k_aggr2<<<nb_w, TB>>>(W2, b2, out);
}